// round 12
// baseline (speedup 1.0000x reference)
#include <cuda_runtime.h>
#include <cuda_fp16.h>
#include <math.h>
#include <stdint.h>

#define NN 50000
#define NE 800000
#define LDS_S 66     // k4 staging stride
#define K1S   68     // k1 staging stride (16B-aligned rows)

typedef unsigned long long u64;

// ---------------- scratch (device globals) ----------------
__device__ float g_f0[NN * 64];
__device__ float g_f1[NN * 192];          // [n][3][64]
__device__ float g_agg0[NN * 64];
__device__ float g_agg1[NN * 192];        // [n][3][64]
__device__ float g_z[NN * 8];
__device__ __half g_wattn_h[256000000];   // E*320
__device__ u64 g_wpk[72832];              // packed (w,w) weights

// packed-weight offsets (u64 elements)
#define OFF_W1    0        // 50x64
#define OFF_W2    3200     // 64x64
#define OFF_WDEG  7296     // 64x128
#define OFF_WATTN 15488    // 64x320
#define OFF_P0    35968    // 64x64
#define OFF_P1    40064    // 64x64
#define OFF_OP0   44160    // 64x64
#define OFF_OP1   48256    // 64x64
#define OFF_W1S   52352    // 64x128
#define OFF_W1V   60544    // 64x64
#define OFF_W2S   64640    // 64x64
#define OFF_W2V   68736    // 64x64
#define WPK_TOTAL 72832

// ---------------- helpers ----------------
__device__ __forceinline__ float siluf(float x) { return __fdividef(x, 1.f + __expf(-x)); }
__device__ __forceinline__ float sigf(float x) { return __fdividef(1.f, 1.f + __expf(-x)); }

__device__ __forceinline__ u64 pk(float x) {
    u64 r; asm("mov.b64 %0, {%1, %1};" : "=l"(r) : "f"(x)); return r;
}
__device__ __forceinline__ void fma2(u64& d, u64 a, u64 b) {
    asm("fma.rn.f32x2 %0, %1, %2, %0;" : "+l"(d) : "l"(a), "l"(b));
}
__device__ __forceinline__ float2 up(u64 a) {
    float2 v; asm("mov.b64 {%0, %1}, %2;" : "=f"(v.x), "=f"(v.y) : "l"(a)); return v;
}

__device__ __forceinline__ void red_v2(float* p, float a, float b) {
    asm volatile("{ .reg .u64 q; cvta.to.global.u64 q, %0; red.global.add.v2.f32 [q], {%1, %2}; }"
                 :: "l"(p), "f"(a), "f"(b) : "memory");
}
__device__ __forceinline__ void red_v4(float* p, float a, float b, float c, float d) {
    asm volatile("{ .reg .u64 q; cvta.to.global.u64 q, %0; red.global.add.v4.f32 [q], {%1, %2, %3, %4}; }"
                 :: "l"(p), "f"(a), "f"(b), "f"(c), "f"(d) : "memory");
}

// ---------------- K0: init node state ----------------
__global__ void k0_init(const float* __restrict__ embed_W, const int* __restrict__ node_atom) {
    int stride = gridDim.x * blockDim.x;
    for (int i = blockIdx.x * blockDim.x + threadIdx.x; i < NN * 192; i += stride) {
        g_f1[i] = 0.f;
        g_agg1[i] = 0.f;
        if (i < NN * 64) {
            int n = i >> 6, c = i & 63;
            g_f0[i] = embed_W[node_atom[n] * 64 + c];
            g_agg0[i] = 0.f;
        }
        if (i < NN * 8) g_z[i] = 0.f;
    }
}

// ---------------- K0w: prepack duplicated weights ----------------
__global__ void k0_wpack(
    const float* __restrict__ W1, const float* __restrict__ W2,
    const float* __restrict__ Wdeg, const float* __restrict__ Wattn,
    const float* __restrict__ P0, const float* __restrict__ P1,
    const float* __restrict__ OP0, const float* __restrict__ OP1,
    const float* __restrict__ W1s, const float* __restrict__ W1v,
    const float* __restrict__ W2s, const float* __restrict__ W2v)
{
    int i = blockIdx.x * 256 + threadIdx.x;
    if (i >= WPK_TOTAL) return;
    float v;
    if (i < OFF_W2)         v = W1[i];
    else if (i < OFF_WDEG)  v = W2[i - OFF_W2];
    else if (i < OFF_WATTN) v = Wdeg[i - OFF_WDEG];
    else if (i < OFF_P0)    v = Wattn[i - OFF_WATTN];
    else if (i < OFF_P1)    v = P0[i - OFF_P0];
    else if (i < OFF_OP0)   v = P1[i - OFF_P1];
    else if (i < OFF_OP1)   v = OP0[i - OFF_OP0];
    else if (i < OFF_W1S)   v = OP1[i - OFF_OP1];
    else if (i < OFF_W1V)   v = W1s[i - OFF_W1S];
    else if (i < OFF_W2S)   v = W1v[i - OFF_W1V];
    else if (i < OFF_W2V)   v = W2s[i - OFF_W2S];
    else                    v = W2v[i - OFF_W2V];
    g_wpk[i] = pk(v);
}

// ---------------- k1 GEMM: packed B, LDS.128 A, 8 edges x 4 cols ----------------
__device__ __forceinline__ void gemm_pk(const float* __restrict__ As, int eA,
                                        const u64* __restrict__ Bpk, int ldb,
                                        int colbase, int c4, int K,
                                        u64 acc[4][4]) {
#pragma unroll
    for (int p = 0; p < 4; p++)
#pragma unroll
        for (int j = 0; j < 4; j++) acc[p][j] = 0ull;
    const u64* Bp = Bpk + colbase + c4;
#pragma unroll 4
    for (int k = 0; k < K; k++) {
        const ulonglong2* ap = reinterpret_cast<const ulonglong2*>(As + k * K1S + eA);
        ulonglong2 A01 = ap[0], A23 = ap[1];
        ulonglong2 B01 = *reinterpret_cast<const ulonglong2*>(Bp + k * ldb);
        ulonglong2 B23 = *reinterpret_cast<const ulonglong2*>(Bp + k * ldb + 2);
        fma2(acc[0][0], A01.x, B01.x); fma2(acc[0][1], A01.x, B01.y); fma2(acc[0][2], A01.x, B23.x); fma2(acc[0][3], A01.x, B23.y);
        fma2(acc[1][0], A01.y, B01.x); fma2(acc[1][1], A01.y, B01.y); fma2(acc[1][2], A01.y, B23.x); fma2(acc[1][3], A01.y, B23.y);
        fma2(acc[2][0], A23.x, B01.x); fma2(acc[2][1], A23.x, B01.y); fma2(acc[2][2], A23.x, B23.x); fma2(acc[2][3], A23.x, B23.y);
        fma2(acc[3][0], A23.y, B01.x); fma2(acc[3][1], A23.y, B01.y); fma2(acc[3][2], A23.y, B23.x); fma2(acc[3][3], A23.y, B23.y);
    }
}

// k4 GEMM: packed B, 4 rows (2 pairs) per thread, K=64, stride LDS_S
__device__ __forceinline__ void gemm_t2(const float* __restrict__ As, int eA,
                                        const u64* __restrict__ Bpk, int ldb,
                                        int colbase, int c4,
                                        u64 acc[2][4]) {
#pragma unroll
    for (int p = 0; p < 2; p++)
#pragma unroll
        for (int j = 0; j < 4; j++) acc[p][j] = 0ull;
    const u64* Bp = Bpk + colbase + c4;
#pragma unroll 4
    for (int k = 0; k < 64; k++) {
        const u64* ap = reinterpret_cast<const u64*>(As + k * LDS_S + eA);
        u64 a0 = ap[0], a1 = ap[1];
        ulonglong2 B01 = *reinterpret_cast<const ulonglong2*>(Bp + k * ldb);
        ulonglong2 B23 = *reinterpret_cast<const ulonglong2*>(Bp + k * ldb + 2);
        fma2(acc[0][0], a0, B01.x); fma2(acc[0][1], a0, B01.y); fma2(acc[0][2], a0, B23.x); fma2(acc[0][3], a0, B23.y);
        fma2(acc[1][0], a1, B01.x); fma2(acc[1][1], a1, B01.y); fma2(acc[1][2], a1, B23.x); fma2(acc[1][3], a1, B23.y);
    }
}

// ---------------- K1: edge-tiled radial MLP + degree scatter + w_attn ----------------
__global__ void __launch_bounds__(128) k1_edge(
    const float* __restrict__ pos, const float* __restrict__ exp_w,
    const float* __restrict__ b1, const float* __restrict__ b2,
    const float* __restrict__ bdeg, const float* __restrict__ battn,
    const int* __restrict__ esrc, const int* __restrict__ edst)
{
    __shared__ float SA[64 * K1S];
    __shared__ float SB[64 * K1S];
    __shared__ float sy[3][64];
    __shared__ int sdst[64];
    __shared__ float stmp[2][64];

    int tid = threadIdx.x;
    int cg = tid & 15, c4 = cg << 2;
    int eg = tid >> 4, eA = eg << 3;
    int ebase = blockIdx.x * 64;

    if (tid < 64) {
        int e = ebase + tid;
        int s = esrc[e], d = edst[e];
        float vx = pos[d * 3 + 0] - pos[s * 3 + 0];
        float vy = pos[d * 3 + 1] - pos[s * 3 + 1];
        float vz = pos[d * 3 + 2] - pos[s * 3 + 2];
        float dist = sqrtf(vx * vx + vy * vy + vz * vz + 1e-9f);
        float ri = 1.f / dist;
        const float PI_ = 3.14159265358979323846f;
        float cut = (dist < 5.0f) ? 0.5f * (__cosf(PI_ * dist * 0.2f) + 1.f) : 0.f;
        sdst[tid] = d;
        sy[0][tid] = vx * ri; sy[1][tid] = vy * ri; sy[2][tid] = vz * ri;
        stmp[0][tid] = cut;
        stmp[1][tid] = __expf(-dist);
    }
    __syncthreads();

    {
        const float START = 0.006737946999085467f;
        const float STEP = (1.0f - START) / 49.0f;
        const float BETA = 1.0f / ((0.04f * (1.0f - START)) * (0.04f * (1.0f - START)));
        int er = tid & 63, k0 = tid >> 6;
        float cut = stmp[0][er], expd = stmp[1][er];
        for (int k = k0; k < 50; k += 2) {
            float t = expd - (START + (float)k * STEP);
            SA[k * K1S + er] = cut * __expf(-BETA * t * t);
        }
    }
    __syncthreads();

    u64 acc[4][4];

    // GEMM1: rbf(50) -> 64, silu -> SB
    gemm_pk(SA, eA, g_wpk + OFF_W1, 64, 0, c4, 50, acc);
    {
#pragma unroll
        for (int j = 0; j < 4; j++) {
            float bb = b1[c4 + j];
#pragma unroll
            for (int p = 0; p < 4; p++) {
                float2 v = up(acc[p][j]);
                v.x = siluf(v.x + bb); v.y = siluf(v.y + bb);
                *reinterpret_cast<float2*>(&SB[(c4 + j) * K1S + eA + 2 * p]) = v;
            }
        }
    }
    __syncthreads();

    // GEMM2: 64 -> 64, silu -> SA (h2)
    gemm_pk(SB, eA, g_wpk + OFF_W2, 64, 0, c4, 64, acc);
    {
#pragma unroll
        for (int j = 0; j < 4; j++) {
            float bb = b2[c4 + j];
#pragma unroll
            for (int p = 0; p < 4; p++) {
                float2 v = up(acc[p][j]);
                v.x = siluf(v.x + bb); v.y = siluf(v.y + bb);
                *reinterpret_cast<float2*>(&SA[(c4 + j) * K1S + eA + 2 * p]) = v;
            }
        }
    }
    __syncthreads();

    // w_attn: 5 chunks of 64 -> fp16 global
    for (int ch = 0; ch < 5; ch++) {
        gemm_pk(SA, eA, g_wpk + OFF_WATTN, 320, ch * 64, c4, 64, acc);
        int col = ch * 64 + c4;
        float b0v = battn[col], b1v = battn[col + 1], b2v = battn[col + 2], b3v = battn[col + 3];
#pragma unroll
        for (int p = 0; p < 4; p++) {
            float2 v0 = up(acc[p][0]), v1 = up(acc[p][1]), v2 = up(acc[p][2]), v3 = up(acc[p][3]);
            long long wbA = (long long)(ebase + eA + 2 * p) * 320 + col;
            long long wbB = wbA + 320;
            *reinterpret_cast<__half2*>(&g_wattn_h[wbA])     = __floats2half2_rn(v0.x + b0v, v1.x + b1v);
            *reinterpret_cast<__half2*>(&g_wattn_h[wbA + 2]) = __floats2half2_rn(v2.x + b2v, v3.x + b3v);
            *reinterpret_cast<__half2*>(&g_wattn_h[wbB])     = __floats2half2_rn(v0.y + b0v, v1.y + b1v);
            *reinterpret_cast<__half2*>(&g_wattn_h[wbB + 2]) = __floats2half2_rn(v2.y + b2v, v3.y + b3v);
        }
    }

    const float INV = 0.25f;

    // deg chunk 0: e0 -> SB
    gemm_pk(SA, eA, g_wpk + OFF_WDEG, 128, 0, c4, 64, acc);
    {
#pragma unroll
        for (int j = 0; j < 4; j++) {
            float bb = bdeg[c4 + j], ee = exp_w[c4 + j];
#pragma unroll
            for (int p = 0; p < 4; p++) {
                float2 v = up(acc[p][j]);
                v.x = (v.x + bb) * ee; v.y = (v.y + bb) * ee;
                *reinterpret_cast<float2*>(&SB[(c4 + j) * K1S + eA + 2 * p]) = v;
            }
        }
    }
    __syncthreads();

    // e0 @ P0 -> red.v4 scatter to f0
    gemm_pk(SB, eA, g_wpk + OFF_P0, 64, 0, c4, 64, acc);
#pragma unroll
    for (int p = 0; p < 4; p++) {
        int dA = sdst[eA + 2 * p], dB = sdst[eA + 2 * p + 1];
        float2 v0 = up(acc[p][0]), v1 = up(acc[p][1]), v2 = up(acc[p][2]), v3 = up(acc[p][3]);
        red_v4(&g_f0[dA * 64 + c4], INV * v0.x, INV * v1.x, INV * v2.x, INV * v3.x);
        red_v4(&g_f0[dB * 64 + c4], INV * v0.y, INV * v1.y, INV * v2.y, INV * v3.y);
    }
    __syncthreads();

    // deg chunk 1: e1 -> SB
    gemm_pk(SA, eA, g_wpk + OFF_WDEG, 128, 64, c4, 64, acc);
    {
#pragma unroll
        for (int j = 0; j < 4; j++) {
            float bb = bdeg[64 + c4 + j], ee = exp_w[c4 + j];
#pragma unroll
            for (int p = 0; p < 4; p++) {
                float2 v = up(acc[p][j]);
                v.x = (v.x + bb) * ee; v.y = (v.y + bb) * ee;
                *reinterpret_cast<float2*>(&SB[(c4 + j) * K1S + eA + 2 * p]) = v;
            }
        }
    }
    __syncthreads();

    // e1 @ P1, times Y -> red.v4 scatter to f1 ([n][3][64])
    gemm_pk(SB, eA, g_wpk + OFF_P1, 64, 0, c4, 64, acc);
#pragma unroll
    for (int p = 0; p < 4; p++) {
        float2 v0 = up(acc[p][0]), v1 = up(acc[p][1]), v2 = up(acc[p][2]), v3 = up(acc[p][3]);
#pragma unroll
        for (int half = 0; half < 2; half++) {
            int el = eA + 2 * p + half;
            int d = sdst[el];
            float a0 = INV * (half ? v0.y : v0.x);
            float a1 = INV * (half ? v1.y : v1.x);
            float a2 = INV * (half ? v2.y : v2.x);
            float a3 = INV * (half ? v3.y : v3.x);
            float* pp = &g_f1[d * 192];
#pragma unroll
            for (int i = 0; i < 3; i++) {
                float yy = sy[i][el];
                red_v4(pp + i * 64 + c4, a0 * yy, a1 * yy, a2 * yy, a3 * yy);
            }
        }
    }
}

// ---------------- K2: fused messages + softmax-weight + aggregation ----------------
__global__ void __launch_bounds__(256) k2_fused(
    const float* __restrict__ pos, const float* __restrict__ alpha_dot,
    const int* __restrict__ esrc, const int* __restrict__ edst)
{
    int warp = threadIdx.x >> 5, lane = threadIdx.x & 31;
    int e = blockIdx.x * 8 + warp;
    if (e >= NE) return;
    int s = esrc[e], d = edst[e];
    float vx = pos[d * 3 + 0] - pos[s * 3 + 0];
    float vy = pos[d * 3 + 1] - pos[s * 3 + 1];
    float vz = pos[d * 3 + 2] - pos[s * 3 + 2];
    float ri = rsqrtf(vx * vx + vy * vy + vz * vz + 1e-9f);
    float y0 = vx * ri, y1 = vy * ri, y2 = vz * ri;

    int c = lane << 1;
    float2 s0 = *reinterpret_cast<const float2*>(&g_f0[s * 64 + c]);
    const float* f1p = &g_f1[s * 192 + c];
    float2 sv0 = *reinterpret_cast<const float2*>(f1p + 0 * 64);
    float2 sv1 = *reinterpret_cast<const float2*>(f1p + 1 * 64);
    float2 sv2 = *reinterpret_cast<const float2*>(f1p + 2 * 64);

    const __half2* wp = reinterpret_cast<const __half2*>(&g_wattn_h[(long long)e * 320 + c]);
    float2 w0 = __half22float2(wp[0]);
    float2 w1 = __half22float2(wp[32]);
    float2 w2 = __half22float2(wp[64]);
    float2 w3 = __half22float2(wp[96]);
    float2 w4 = __half22float2(wp[128]);

    const float IS3 = 0.57735026918962576f;
    const float IS2 = 0.70710678118654752f;

    float dvx = sv0.x * y0 + sv1.x * y1 + sv2.x * y2;
    float dvy = sv0.y * y0 + sv1.y * y1 + sv2.y * y2;
    float m0x = w0.x * s0.x + w3.x * dvx * IS3;
    float m0y = w0.y * s0.y + w3.y * dvy * IS3;

    float cx0x = sv1.x * y2 - sv2.x * y1, cx1x = sv2.x * y0 - sv0.x * y2, cx2x = sv0.x * y1 - sv1.x * y0;
    float cx0y = sv1.y * y2 - sv2.y * y1, cx1y = sv2.y * y0 - sv0.y * y2, cx2y = sv0.y * y1 - sv1.y * y0;
    float w1sx = w1.x * s0.x, w1sy = w1.y * s0.y;
    float m1x0 = w1sx * y0 + w2.x * sv0.x + w4.x * cx0x * IS2;
    float m1x1 = w1sx * y1 + w2.x * sv1.x + w4.x * cx1x * IS2;
    float m1x2 = w1sx * y2 + w2.x * sv2.x + w4.x * cx2x * IS2;
    float m1y0 = w1sy * y0 + w2.y * sv0.y + w4.y * cx0y * IS2;
    float m1y1 = w1sy * y1 + w2.y * sv1.y + w4.y * cx1y * IS2;
    float m1y2 = w1sy * y2 + w2.y * sv2.y + w4.y * cx2y * IS2;

    float slrx = 0.2f * m0x + 0.8f * m0x * sigf(m0x);
    float slry = 0.2f * m0y + 0.8f * m0y * sigf(m0y);
    float p = slrx * alpha_dot[c] + slry * alpha_dot[c + 1];
    p += __shfl_xor_sync(0xffffffffu, p, 2);
    p += __shfl_xor_sync(0xffffffffu, p, 1);
    float ea = __expf(p);

    if ((lane & 3) == 0) atomicAdd(&g_z[d * 8 + (lane >> 2)], ea);

    red_v2(&g_agg0[d * 64 + c], ea * m0x, ea * m0y);
    float* ap = &g_agg1[d * 192 + c];
    red_v2(ap + 0 * 64, ea * m1x0, ea * m1y0);
    red_v2(ap + 1 * 64, ea * m1x1, ea * m1y1);
    red_v2(ap + 2 * 64, ea * m1x2, ea * m1y2);
}

// ---------------- K4: tiled node update (64 nodes / block) ----------------
#define SOFF_T   0
#define SOFF_F0  4224
#define SOFF_F10 8448
#define SOFF_F11 12672
#define SOFF_F12 16896
#define SOFF_G   21120
#define K4_SMEM  (25344 * 4)

__global__ void __launch_bounds__(256) k4_node(
    const float* __restrict__ b1s, const float* __restrict__ b2s,
    float* __restrict__ out)
{
    extern __shared__ float sm4[];
    float* T  = sm4 + SOFF_T;
    float* F0 = sm4 + SOFF_F0;
    float* F1a = sm4 + SOFF_F10;
    float* F1b = sm4 + SOFF_F11;
    float* F1c = sm4 + SOFF_F12;
    float* G  = sm4 + SOFF_G;
    float* F1arr[3] = {F1a, F1b, F1c};

    int tid = threadIdx.x;
    int cg = tid & 15, c4 = cg << 2;
    int eA = (tid >> 4) << 2;
    int nbase = blockIdx.x * 64;

    for (int idx = tid; idx < 4096; idx += 256) {
        int node = idx >> 6, c = idx & 63;
        int n = nbase + node; if (n >= NN) n = NN - 1;
        float z = g_z[n * 8 + (c >> 3)];
        float rz = z > 0.f ? __fdividef(1.f, z) : 0.f;
        T[c * LDS_S + node]   = g_agg0[n * 64 + c] * rz;
        F1a[c * LDS_S + node] = g_agg1[n * 192 + c] * rz;
        F1b[c * LDS_S + node] = g_agg1[n * 192 + 64 + c] * rz;
        F1c[c * LDS_S + node] = g_agg1[n * 192 + 128 + c] * rz;
    }
    __syncthreads();

    u64 acc[2][4];

    gemm_t2(T, eA, g_wpk + OFF_OP0, 64, 0, c4, acc);
#pragma unroll
    for (int p = 0; p < 2; p++) {
        int na = nbase + eA + 2 * p, nb = na + 1;
        int la = na < NN ? na : NN - 1, lb = nb < NN ? nb : NN - 1;
        float4 ra = *reinterpret_cast<const float4*>(&g_f0[la * 64 + c4]);
        float4 rb = *reinterpret_cast<const float4*>(&g_f0[lb * 64 + c4]);
        float2 v0 = up(acc[p][0]), v1 = up(acc[p][1]), v2 = up(acc[p][2]), v3 = up(acc[p][3]);
        int ea2 = eA + 2 * p;
        F0[(c4 + 0) * LDS_S + ea2] = v0.x + ra.x;  F0[(c4 + 0) * LDS_S + ea2 + 1] = v0.y + rb.x;
        F0[(c4 + 1) * LDS_S + ea2] = v1.x + ra.y;  F0[(c4 + 1) * LDS_S + ea2 + 1] = v1.y + rb.y;
        F0[(c4 + 2) * LDS_S + ea2] = v2.x + ra.z;  F0[(c4 + 2) * LDS_S + ea2 + 1] = v2.y + rb.z;
        F0[(c4 + 3) * LDS_S + ea2] = v3.x + ra.w;  F0[(c4 + 3) * LDS_S + ea2 + 1] = v3.y + rb.w;
    }

#pragma unroll
    for (int i = 0; i < 3; i++) {
        float* Fi = F1arr[i];
        gemm_t2(Fi, eA, g_wpk + OFF_OP1, 64, 0, c4, acc);
        __syncthreads();
#pragma unroll
        for (int p = 0; p < 2; p++) {
            int na = nbase + eA + 2 * p, nb = na + 1;
            int la = na < NN ? na : NN - 1, lb = nb < NN ? nb : NN - 1;
            float4 ra = *reinterpret_cast<const float4*>(&g_f1[la * 192 + i * 64 + c4]);
            float4 rb = *reinterpret_cast<const float4*>(&g_f1[lb * 192 + i * 64 + c4]);
            float2 v0 = up(acc[p][0]), v1 = up(acc[p][1]), v2 = up(acc[p][2]), v3 = up(acc[p][3]);
            int ea2 = eA + 2 * p;
            Fi[(c4 + 0) * LDS_S + ea2] = v0.x + ra.x;  Fi[(c4 + 0) * LDS_S + ea2 + 1] = v0.y + rb.x;
            Fi[(c4 + 1) * LDS_S + ea2] = v1.x + ra.y;  Fi[(c4 + 1) * LDS_S + ea2 + 1] = v1.y + rb.y;
            Fi[(c4 + 2) * LDS_S + ea2] = v2.x + ra.z;  Fi[(c4 + 2) * LDS_S + ea2 + 1] = v2.y + rb.z;
            Fi[(c4 + 3) * LDS_S + ea2] = v3.x + ra.w;  Fi[(c4 + 3) * LDS_S + ea2 + 1] = v3.y + rb.w;
        }
        __syncthreads();
    }

    gemm_t2(F0, eA, g_wpk + OFF_W1S, 128, 0, c4, acc);
    {
#pragma unroll
        for (int j = 0; j < 4; j++) {
            float bb = b1s[c4 + j];
#pragma unroll
            for (int p = 0; p < 2; p++) {
                float2 v = up(acc[p][j]);
                T[(c4 + j) * LDS_S + eA + 2 * p]     = siluf(v.x + bb);
                T[(c4 + j) * LDS_S + eA + 2 * p + 1] = siluf(v.y + bb);
            }
        }
    }
    gemm_t2(F0, eA, g_wpk + OFF_W1S, 128, 64, c4, acc);
    {
#pragma unroll
        for (int j = 0; j < 4; j++) {
            float bb = b1s[64 + c4 + j];
#pragma unroll
            for (int p = 0; p < 2; p++) {
                float2 v = up(acc[p][j]);
                G[(c4 + j) * LDS_S + eA + 2 * p]     = sigf(v.x + bb);
                G[(c4 + j) * LDS_S + eA + 2 * p + 1] = sigf(v.y + bb);
            }
        }
    }
    __syncthreads();

    gemm_t2(T, eA, g_wpk + OFF_W2S, 64, 0, c4, acc);
#pragma unroll
    for (int p = 0; p < 2; p++) {
        float2 v0 = up(acc[p][0]), v1 = up(acc[p][1]), v2 = up(acc[p][2]), v3 = up(acc[p][3]);
#pragma unroll
        for (int half = 0; half < 2; half++) {
            int node = eA + 2 * p + half;
            int n = nbase + node;
            if (n < NN) {
                float4 o;
                o.x = (half ? v0.y : v0.x) + b2s[c4 + 0] + F0[(c4 + 0) * LDS_S + node];
                o.y = (half ? v1.y : v1.x) + b2s[c4 + 1] + F0[(c4 + 1) * LDS_S + node];
                o.z = (half ? v2.y : v2.x) + b2s[c4 + 2] + F0[(c4 + 2) * LDS_S + node];
                o.w = (half ? v3.y : v3.x) + b2s[c4 + 3] + F0[(c4 + 3) * LDS_S + node];
                *reinterpret_cast<float4*>(&out[(long long)n * 256 + c4]) = o;
            }
        }
    }

#pragma unroll
    for (int i = 0; i < 3; i++) {
        float* Fi = F1arr[i];
        gemm_t2(Fi, eA, g_wpk + OFF_W1V, 64, 0, c4, acc);
        __syncthreads();
        {
#pragma unroll
            for (int j = 0; j < 4; j++) {
#pragma unroll
                for (int p = 0; p < 2; p++) {
                    float2 v = up(acc[p][j]);
                    int node = eA + 2 * p;
                    T[(c4 + j) * LDS_S + node]     = v.x * G[(c4 + j) * LDS_S + node];
                    T[(c4 + j) * LDS_S + node + 1] = v.y * G[(c4 + j) * LDS_S + node + 1];
                }
            }
        }
        __syncthreads();
        gemm_t2(T, eA, g_wpk + OFF_W2V, 64, 0, c4, acc);
#pragma unroll
        for (int p = 0; p < 2; p++) {
            float2 v0 = up(acc[p][0]), v1 = up(acc[p][1]), v2 = up(acc[p][2]), v3 = up(acc[p][3]);
#pragma unroll
            for (int half = 0; half < 2; half++) {
                int node = eA + 2 * p + half;
                int n = nbase + node;
                if (n < NN) {
                    long long ob = (long long)n * 256 + 64;
                    out[ob + (c4 + 0) * 3 + i] = (half ? v0.y : v0.x) + Fi[(c4 + 0) * LDS_S + node];
                    out[ob + (c4 + 1) * 3 + i] = (half ? v1.y : v1.x) + Fi[(c4 + 1) * LDS_S + node];
                    out[ob + (c4 + 2) * 3 + i] = (half ? v2.y : v2.x) + Fi[(c4 + 2) * LDS_S + node];
                    out[ob + (c4 + 3) * 3 + i] = (half ? v3.y : v3.x) + Fi[(c4 + 3) * LDS_S + node];
                }
            }
        }
    }
}

// ---------------- launch ----------------
extern "C" void kernel_launch(void* const* d_in, const int* in_sizes, int n_in,
                              void* d_out, int out_size) {
    const float* pos       = (const float*)d_in[0];
    const float* embed_W   = (const float*)d_in[1];
    const float* exp_w     = (const float*)d_in[2];
    const float* rad_W1    = (const float*)d_in[3];
    const float* rad_b1    = (const float*)d_in[4];
    const float* rad_W2    = (const float*)d_in[5];
    const float* rad_b2    = (const float*)d_in[6];
    const float* rad_Wdeg  = (const float*)d_in[7];
    const float* rad_bdeg  = (const float*)d_in[8];
    const float* rad_Wattn = (const float*)d_in[9];
    const float* rad_battn = (const float*)d_in[10];
    const float* deg_proj0 = (const float*)d_in[11];
    const float* deg_proj1 = (const float*)d_in[12];
    const float* alpha_dot = (const float*)d_in[13];
    const float* out_proj0 = (const float*)d_in[14];
    const float* out_proj1 = (const float*)d_in[15];
    const float* ffn_W1s   = (const float*)d_in[16];
    const float* ffn_b1s   = (const float*)d_in[17];
    const float* ffn_W1v   = (const float*)d_in[18];
    const float* ffn_W2s   = (const float*)d_in[19];
    const float* ffn_b2s   = (const float*)d_in[20];
    const float* ffn_W2v   = (const float*)d_in[21];
    const int* node_atom   = (const int*)d_in[22];
    const int* edge_src    = (const int*)d_in[23];
    const int* edge_dst    = (const int*)d_in[24];
    float* out = (float*)d_out;

    cudaFuncSetAttribute(k4_node, cudaFuncAttributeMaxDynamicSharedMemorySize, K4_SMEM);

    k0_init<<<1024, 256>>>(embed_W, node_atom);
    k0_wpack<<<(WPK_TOTAL + 255) / 256, 256>>>(rad_W1, rad_W2, rad_Wdeg, rad_Wattn,
                                               deg_proj0, deg_proj1,
                                               out_proj0, out_proj1, ffn_W1s, ffn_W1v,
                                               ffn_W2s, ffn_W2v);
    k1_edge<<<NE / 64, 128>>>(pos, exp_w, rad_b1, rad_b2, rad_bdeg, rad_battn,
                              edge_src, edge_dst);
    k2_fused<<<NE / 8, 256>>>(pos, alpha_dot, edge_src, edge_dst);
    k4_node<<<(NN + 63) / 64, 256, K4_SMEM>>>(ffn_b1s, ffn_b2s, out);
}

// round 13
// speedup vs baseline: 1.7175x; 1.7175x over previous
#include <cuda_runtime.h>
#include <cuda_fp16.h>
#include <math.h>
#include <stdint.h>

#define NN 50000
#define NE 800000
#define LDS_S 66

// ---------------- scratch (device globals) ----------------
__device__ float g_f0[NN * 64];
__device__ float g_f1[NN * 192];          // [n][3][64]
__device__ float g_agg0[NN * 64];
__device__ float g_agg1[NN * 192];        // [n][3][64]
__device__ float g_z[NN * 8];
__device__ __half g_wattn_h[256000000];   // E*320

typedef unsigned long long u64;

// ---------------- helpers ----------------
__device__ __forceinline__ float siluf(float x) { return __fdividef(x, 1.f + __expf(-x)); }
__device__ __forceinline__ float sigf(float x) { return __fdividef(1.f, 1.f + __expf(-x)); }

__device__ __forceinline__ u64 pk(float x) {
    u64 r; asm("mov.b64 %0, {%1, %1};" : "=l"(r) : "f"(x)); return r;
}
__device__ __forceinline__ void fma2(u64& d, u64 a, u64 b) {
    asm("fma.rn.f32x2 %0, %1, %2, %0;" : "+l"(d) : "l"(a), "l"(b));
}
__device__ __forceinline__ float2 up(u64 a) {
    float2 v; asm("mov.b64 {%0, %1}, %2;" : "=f"(v.x), "=f"(v.y) : "l"(a)); return v;
}

__device__ __forceinline__ void red_v2(float* p, float a, float b) {
    asm volatile("{ .reg .u64 q; cvta.to.global.u64 q, %0; red.global.add.v2.f32 [q], {%1, %2}; }"
                 :: "l"(p), "f"(a), "f"(b) : "memory");
}
__device__ __forceinline__ void red_v4(float* p, float a, float b, float c, float d) {
    asm volatile("{ .reg .u64 q; cvta.to.global.u64 q, %0; red.global.add.v4.f32 [q], {%1, %2, %3, %4}; }"
                 :: "l"(p), "f"(a), "f"(b), "f"(c), "f"(d) : "memory");
}

// ---------------- K0: init node state ----------------
__global__ void k0_init(const float* __restrict__ embed_W, const int* __restrict__ node_atom) {
    int stride = gridDim.x * blockDim.x;
    for (int i = blockIdx.x * blockDim.x + threadIdx.x; i < NN * 192; i += stride) {
        g_f1[i] = 0.f;
        g_agg1[i] = 0.f;
        if (i < NN * 64) {
            int n = i >> 6, c = i & 63;
            g_f0[i] = embed_W[node_atom[n] * 64 + c];
            g_agg0[i] = 0.f;
        }
        if (i < NN * 8) g_z[i] = 0.f;
    }
}

// ---------------- k-major GEMM, 8 rows (4 pairs) per thread ----------------
__device__ __forceinline__ void gemm_t(const float* __restrict__ As, int eA,
                                       const float* __restrict__ Bg, int ldb,
                                       int colbase, int c4, int K,
                                       u64 acc[4][4]) {
#pragma unroll
    for (int p = 0; p < 4; p++)
#pragma unroll
        for (int j = 0; j < 4; j++) acc[p][j] = 0ull;
    const float* Bp = Bg + colbase + c4;
#pragma unroll 4
    for (int k = 0; k < K; k++) {
        const u64* ap = reinterpret_cast<const u64*>(As + k * LDS_S + eA);
        u64 a0 = ap[0], a1 = ap[1], a2 = ap[2], a3 = ap[3];
        float4 b = *reinterpret_cast<const float4*>(Bp + k * ldb);
        u64 bx = pk(b.x), by = pk(b.y), bz = pk(b.z), bw = pk(b.w);
        fma2(acc[0][0], a0, bx); fma2(acc[0][1], a0, by); fma2(acc[0][2], a0, bz); fma2(acc[0][3], a0, bw);
        fma2(acc[1][0], a1, bx); fma2(acc[1][1], a1, by); fma2(acc[1][2], a1, bz); fma2(acc[1][3], a1, bw);
        fma2(acc[2][0], a2, bx); fma2(acc[2][1], a2, by); fma2(acc[2][2], a2, bz); fma2(acc[2][3], a2, bw);
        fma2(acc[3][0], a3, bx); fma2(acc[3][1], a3, by); fma2(acc[3][2], a3, bz); fma2(acc[3][3], a3, bw);
    }
}

// k-major GEMM, 4 rows (2 pairs) per thread, K=64
__device__ __forceinline__ void gemm_t2(const float* __restrict__ As, int eA,
                                        const float* __restrict__ Bg, int ldb,
                                        int colbase, int c4,
                                        u64 acc[2][4]) {
#pragma unroll
    for (int p = 0; p < 2; p++)
#pragma unroll
        for (int j = 0; j < 4; j++) acc[p][j] = 0ull;
    const float* Bp = Bg + colbase + c4;
#pragma unroll 4
    for (int k = 0; k < 64; k++) {
        const u64* ap = reinterpret_cast<const u64*>(As + k * LDS_S + eA);
        u64 a0 = ap[0], a1 = ap[1];
        float4 b = *reinterpret_cast<const float4*>(Bp + k * ldb);
        u64 bx = pk(b.x), by = pk(b.y), bz = pk(b.z), bw = pk(b.w);
        fma2(acc[0][0], a0, bx); fma2(acc[0][1], a0, by); fma2(acc[0][2], a0, bz); fma2(acc[0][3], a0, bw);
        fma2(acc[1][0], a1, bx); fma2(acc[1][1], a1, by); fma2(acc[1][2], a1, bz); fma2(acc[1][3], a1, bw);
    }
}

// ---------------- K1: edge-tiled radial MLP + degree scatter + w_attn ----------------
__global__ void __launch_bounds__(128) k1_edge(
    const float* __restrict__ pos, const float* __restrict__ exp_w,
    const float* __restrict__ W1, const float* __restrict__ b1,
    const float* __restrict__ W2, const float* __restrict__ b2,
    const float* __restrict__ Wdeg, const float* __restrict__ bdeg,
    const float* __restrict__ Wattn, const float* __restrict__ battn,
    const float* __restrict__ P0, const float* __restrict__ P1,
    const int* __restrict__ esrc, const int* __restrict__ edst)
{
    __shared__ float SA[64 * LDS_S];
    __shared__ float SB[64 * LDS_S];
    __shared__ float sy[3][64];
    __shared__ int sdst[64];
    __shared__ float stmp[2][64];

    int tid = threadIdx.x;
    int cg = tid & 15, c4 = cg << 2;
    int eg = tid >> 4, eA = eg << 3;
    int ebase = blockIdx.x * 64;

    if (tid < 64) {
        int e = ebase + tid;
        int s = esrc[e], d = edst[e];
        float vx = pos[d * 3 + 0] - pos[s * 3 + 0];
        float vy = pos[d * 3 + 1] - pos[s * 3 + 1];
        float vz = pos[d * 3 + 2] - pos[s * 3 + 2];
        float dist = sqrtf(vx * vx + vy * vy + vz * vz + 1e-9f);
        float ri = 1.f / dist;
        const float PI_ = 3.14159265358979323846f;
        float cut = (dist < 5.0f) ? 0.5f * (__cosf(PI_ * dist * 0.2f) + 1.f) : 0.f;
        sdst[tid] = d;
        sy[0][tid] = vx * ri; sy[1][tid] = vy * ri; sy[2][tid] = vz * ri;
        stmp[0][tid] = cut;
        stmp[1][tid] = __expf(-dist);
    }
    __syncthreads();

    {
        const float START = 0.006737946999085467f;
        const float STEP = (1.0f - START) / 49.0f;
        const float BETA = 1.0f / ((0.04f * (1.0f - START)) * (0.04f * (1.0f - START)));
        int er = tid & 63, k0 = tid >> 6;
        float cut = stmp[0][er], expd = stmp[1][er];
        for (int k = k0; k < 50; k += 2) {
            float t = expd - (START + (float)k * STEP);
            SA[k * LDS_S + er] = cut * __expf(-BETA * t * t);
        }
    }
    __syncthreads();

    u64 acc[4][4];

    gemm_t(SA, eA, W1, 64, 0, c4, 50, acc);
    {
#pragma unroll
        for (int j = 0; j < 4; j++) {
            float bb = b1[c4 + j];
#pragma unroll
            for (int p = 0; p < 4; p++) {
                float2 v = up(acc[p][j]);
                v.x = siluf(v.x + bb); v.y = siluf(v.y + bb);
                *reinterpret_cast<float2*>(&SB[(c4 + j) * LDS_S + eA + 2 * p]) = v;
            }
        }
    }
    __syncthreads();

    gemm_t(SB, eA, W2, 64, 0, c4, 64, acc);
    {
#pragma unroll
        for (int j = 0; j < 4; j++) {
            float bb = b2[c4 + j];
#pragma unroll
            for (int p = 0; p < 4; p++) {
                float2 v = up(acc[p][j]);
                v.x = siluf(v.x + bb); v.y = siluf(v.y + bb);
                *reinterpret_cast<float2*>(&SA[(c4 + j) * LDS_S + eA + 2 * p]) = v;
            }
        }
    }
    __syncthreads();

    for (int ch = 0; ch < 5; ch++) {
        gemm_t(SA, eA, Wattn, 320, ch * 64, c4, 64, acc);
        int col = ch * 64 + c4;
        float b0v = battn[col], b1v = battn[col + 1], b2v = battn[col + 2], b3v = battn[col + 3];
#pragma unroll
        for (int p = 0; p < 4; p++) {
            float2 v0 = up(acc[p][0]), v1 = up(acc[p][1]), v2 = up(acc[p][2]), v3 = up(acc[p][3]);
            long long wbA = (long long)(ebase + eA + 2 * p) * 320 + col;
            long long wbB = wbA + 320;
            *reinterpret_cast<__half2*>(&g_wattn_h[wbA])     = __floats2half2_rn(v0.x + b0v, v1.x + b1v);
            *reinterpret_cast<__half2*>(&g_wattn_h[wbA + 2]) = __floats2half2_rn(v2.x + b2v, v3.x + b3v);
            *reinterpret_cast<__half2*>(&g_wattn_h[wbB])     = __floats2half2_rn(v0.y + b0v, v1.y + b1v);
            *reinterpret_cast<__half2*>(&g_wattn_h[wbB + 2]) = __floats2half2_rn(v2.y + b2v, v3.y + b3v);
        }
    }

    const float INV = 0.25f;

    gemm_t(SA, eA, Wdeg, 128, 0, c4, 64, acc);
    {
#pragma unroll
        for (int j = 0; j < 4; j++) {
            float bb = bdeg[c4 + j], ee = exp_w[c4 + j];
#pragma unroll
            for (int p = 0; p < 4; p++) {
                float2 v = up(acc[p][j]);
                v.x = (v.x + bb) * ee; v.y = (v.y + bb) * ee;
                *reinterpret_cast<float2*>(&SB[(c4 + j) * LDS_S + eA + 2 * p]) = v;
            }
        }
    }
    __syncthreads();

    gemm_t(SB, eA, P0, 64, 0, c4, 64, acc);
#pragma unroll
    for (int p = 0; p < 4; p++) {
        int dA = sdst[eA + 2 * p], dB = sdst[eA + 2 * p + 1];
        float2 v0 = up(acc[p][0]), v1 = up(acc[p][1]), v2 = up(acc[p][2]), v3 = up(acc[p][3]);
        red_v4(&g_f0[dA * 64 + c4], INV * v0.x, INV * v1.x, INV * v2.x, INV * v3.x);
        red_v4(&g_f0[dB * 64 + c4], INV * v0.y, INV * v1.y, INV * v2.y, INV * v3.y);
    }
    __syncthreads();

    gemm_t(SA, eA, Wdeg, 128, 64, c4, 64, acc);
    {
#pragma unroll
        for (int j = 0; j < 4; j++) {
            float bb = bdeg[64 + c4 + j], ee = exp_w[c4 + j];
#pragma unroll
            for (int p = 0; p < 4; p++) {
                float2 v = up(acc[p][j]);
                v.x = (v.x + bb) * ee; v.y = (v.y + bb) * ee;
                *reinterpret_cast<float2*>(&SB[(c4 + j) * LDS_S + eA + 2 * p]) = v;
            }
        }
    }
    __syncthreads();

    gemm_t(SB, eA, P1, 64, 0, c4, 64, acc);
#pragma unroll
    for (int p = 0; p < 4; p++) {
        float2 v0 = up(acc[p][0]), v1 = up(acc[p][1]), v2 = up(acc[p][2]), v3 = up(acc[p][3]);
#pragma unroll
        for (int half = 0; half < 2; half++) {
            int el = eA + 2 * p + half;
            int d = sdst[el];
            float a0 = INV * (half ? v0.y : v0.x);
            float a1 = INV * (half ? v1.y : v1.x);
            float a2 = INV * (half ? v2.y : v2.x);
            float a3 = INV * (half ? v3.y : v3.x);
            float* pp = &g_f1[d * 192];
#pragma unroll
            for (int i = 0; i < 3; i++) {
                float yy = sy[i][el];
                red_v4(pp + i * 64 + c4, a0 * yy, a1 * yy, a2 * yy, a3 * yy);
            }
        }
    }
}

// ---------------- K2: fused messages + softmax-weight + aggregation ----------------
__global__ void __launch_bounds__(256) k2_fused(
    const float* __restrict__ pos, const float* __restrict__ alpha_dot,
    const int* __restrict__ esrc, const int* __restrict__ edst)
{
    int warp = threadIdx.x >> 5, lane = threadIdx.x & 31;
    int e = blockIdx.x * 8 + warp;
    if (e >= NE) return;
    int s = esrc[e], d = edst[e];
    float vx = pos[d * 3 + 0] - pos[s * 3 + 0];
    float vy = pos[d * 3 + 1] - pos[s * 3 + 1];
    float vz = pos[d * 3 + 2] - pos[s * 3 + 2];
    float ri = rsqrtf(vx * vx + vy * vy + vz * vz + 1e-9f);
    float y0 = vx * ri, y1 = vy * ri, y2 = vz * ri;

    int c = lane << 1;
    float2 s0 = *reinterpret_cast<const float2*>(&g_f0[s * 64 + c]);
    const float* f1p = &g_f1[s * 192 + c];
    float2 sv0 = *reinterpret_cast<const float2*>(f1p + 0 * 64);
    float2 sv1 = *reinterpret_cast<const float2*>(f1p + 1 * 64);
    float2 sv2 = *reinterpret_cast<const float2*>(f1p + 2 * 64);

    const __half2* wp = reinterpret_cast<const __half2*>(&g_wattn_h[(long long)e * 320 + c]);
    float2 w0 = __half22float2(wp[0]);
    float2 w1 = __half22float2(wp[32]);
    float2 w2 = __half22float2(wp[64]);
    float2 w3 = __half22float2(wp[96]);
    float2 w4 = __half22float2(wp[128]);

    const float IS3 = 0.57735026918962576f;
    const float IS2 = 0.70710678118654752f;

    float dvx = sv0.x * y0 + sv1.x * y1 + sv2.x * y2;
    float dvy = sv0.y * y0 + sv1.y * y1 + sv2.y * y2;
    float m0x = w0.x * s0.x + w3.x * dvx * IS3;
    float m0y = w0.y * s0.y + w3.y * dvy * IS3;

    float cx0x = sv1.x * y2 - sv2.x * y1, cx1x = sv2.x * y0 - sv0.x * y2, cx2x = sv0.x * y1 - sv1.x * y0;
    float cx0y = sv1.y * y2 - sv2.y * y1, cx1y = sv2.y * y0 - sv0.y * y2, cx2y = sv0.y * y1 - sv1.y * y0;
    float w1sx = w1.x * s0.x, w1sy = w1.y * s0.y;
    float m1x0 = w1sx * y0 + w2.x * sv0.x + w4.x * cx0x * IS2;
    float m1x1 = w1sx * y1 + w2.x * sv1.x + w4.x * cx1x * IS2;
    float m1x2 = w1sx * y2 + w2.x * sv2.x + w4.x * cx2x * IS2;
    float m1y0 = w1sy * y0 + w2.y * sv0.y + w4.y * cx0y * IS2;
    float m1y1 = w1sy * y1 + w2.y * sv1.y + w4.y * cx1y * IS2;
    float m1y2 = w1sy * y2 + w2.y * sv2.y + w4.y * cx2y * IS2;

    float slrx = 0.2f * m0x + 0.8f * m0x * sigf(m0x);
    float slry = 0.2f * m0y + 0.8f * m0y * sigf(m0y);
    float p = slrx * alpha_dot[c] + slry * alpha_dot[c + 1];
    p += __shfl_xor_sync(0xffffffffu, p, 2);
    p += __shfl_xor_sync(0xffffffffu, p, 1);
    float ea = __expf(p);

    if ((lane & 3) == 0) atomicAdd(&g_z[d * 8 + (lane >> 2)], ea);

    red_v2(&g_agg0[d * 64 + c], ea * m0x, ea * m0y);
    float* ap = &g_agg1[d * 192 + c];
    red_v2(ap + 0 * 64, ea * m1x0, ea * m1y0);
    red_v2(ap + 1 * 64, ea * m1x1, ea * m1y1);
    red_v2(ap + 2 * 64, ea * m1x2, ea * m1y2);
}

// ---------------- K4: tiled node update (64 nodes / block) ----------------
#define SOFF_T   0
#define SOFF_F0  4224
#define SOFF_F10 8448
#define SOFF_F11 12672
#define SOFF_F12 16896
#define SOFF_G   21120
#define K4_SMEM  (25344 * 4)

__global__ void __launch_bounds__(256) k4_node(
    const float* __restrict__ P0, const float* __restrict__ P1,
    const float* __restrict__ W1s, const float* __restrict__ b1s,
    const float* __restrict__ W1v, const float* __restrict__ W2s,
    const float* __restrict__ b2s, const float* __restrict__ W2v,
    float* __restrict__ out)
{
    extern __shared__ float sm4[];
    float* T  = sm4 + SOFF_T;
    float* F0 = sm4 + SOFF_F0;
    float* F1a = sm4 + SOFF_F10;
    float* F1b = sm4 + SOFF_F11;
    float* F1c = sm4 + SOFF_F12;
    float* G  = sm4 + SOFF_G;
    float* F1arr[3] = {F1a, F1b, F1c};

    int tid = threadIdx.x;
    int cg = tid & 15, c4 = cg << 2;
    int eA = (tid >> 4) << 2;
    int nbase = blockIdx.x * 64;

    for (int idx = tid; idx < 4096; idx += 256) {
        int node = idx >> 6, c = idx & 63;
        int n = nbase + node; if (n >= NN) n = NN - 1;
        float z = g_z[n * 8 + (c >> 3)];
        float rz = z > 0.f ? __fdividef(1.f, z) : 0.f;
        T[c * LDS_S + node]   = g_agg0[n * 64 + c] * rz;
        F1a[c * LDS_S + node] = g_agg1[n * 192 + c] * rz;
        F1b[c * LDS_S + node] = g_agg1[n * 192 + 64 + c] * rz;
        F1c[c * LDS_S + node] = g_agg1[n * 192 + 128 + c] * rz;
    }
    __syncthreads();

    u64 acc[2][4];

    gemm_t2(T, eA, P0, 64, 0, c4, acc);
#pragma unroll
    for (int p = 0; p < 2; p++) {
        int na = nbase + eA + 2 * p, nb = na + 1;
        int la = na < NN ? na : NN - 1, lb = nb < NN ? nb : NN - 1;
        float4 ra = *reinterpret_cast<const float4*>(&g_f0[la * 64 + c4]);
        float4 rb = *reinterpret_cast<const float4*>(&g_f0[lb * 64 + c4]);
        float2 v0 = up(acc[p][0]), v1 = up(acc[p][1]), v2 = up(acc[p][2]), v3 = up(acc[p][3]);
        int ea2 = eA + 2 * p;
        F0[(c4 + 0) * LDS_S + ea2] = v0.x + ra.x;  F0[(c4 + 0) * LDS_S + ea2 + 1] = v0.y + rb.x;
        F0[(c4 + 1) * LDS_S + ea2] = v1.x + ra.y;  F0[(c4 + 1) * LDS_S + ea2 + 1] = v1.y + rb.y;
        F0[(c4 + 2) * LDS_S + ea2] = v2.x + ra.z;  F0[(c4 + 2) * LDS_S + ea2 + 1] = v2.y + rb.z;
        F0[(c4 + 3) * LDS_S + ea2] = v3.x + ra.w;  F0[(c4 + 3) * LDS_S + ea2 + 1] = v3.y + rb.w;
    }

#pragma unroll
    for (int i = 0; i < 3; i++) {
        float* Fi = F1arr[i];
        gemm_t2(Fi, eA, P1, 64, 0, c4, acc);
        __syncthreads();
#pragma unroll
        for (int p = 0; p < 2; p++) {
            int na = nbase + eA + 2 * p, nb = na + 1;
            int la = na < NN ? na : NN - 1, lb = nb < NN ? nb : NN - 1;
            float4 ra = *reinterpret_cast<const float4*>(&g_f1[la * 192 + i * 64 + c4]);
            float4 rb = *reinterpret_cast<const float4*>(&g_f1[lb * 192 + i * 64 + c4]);
            float2 v0 = up(acc[p][0]), v1 = up(acc[p][1]), v2 = up(acc[p][2]), v3 = up(acc[p][3]);
            int ea2 = eA + 2 * p;
            Fi[(c4 + 0) * LDS_S + ea2] = v0.x + ra.x;  Fi[(c4 + 0) * LDS_S + ea2 + 1] = v0.y + rb.x;
            Fi[(c4 + 1) * LDS_S + ea2] = v1.x + ra.y;  Fi[(c4 + 1) * LDS_S + ea2 + 1] = v1.y + rb.y;
            Fi[(c4 + 2) * LDS_S + ea2] = v2.x + ra.z;  Fi[(c4 + 2) * LDS_S + ea2 + 1] = v2.y + rb.z;
            Fi[(c4 + 3) * LDS_S + ea2] = v3.x + ra.w;  Fi[(c4 + 3) * LDS_S + ea2 + 1] = v3.y + rb.w;
        }
        __syncthreads();
    }

    gemm_t2(F0, eA, W1s, 128, 0, c4, acc);
    {
#pragma unroll
        for (int j = 0; j < 4; j++) {
            float bb = b1s[c4 + j];
#pragma unroll
            for (int p = 0; p < 2; p++) {
                float2 v = up(acc[p][j]);
                T[(c4 + j) * LDS_S + eA + 2 * p]     = siluf(v.x + bb);
                T[(c4 + j) * LDS_S + eA + 2 * p + 1] = siluf(v.y + bb);
            }
        }
    }
    gemm_t2(F0, eA, W1s, 128, 64, c4, acc);
    {
#pragma unroll
        for (int j = 0; j < 4; j++) {
            float bb = b1s[64 + c4 + j];
#pragma unroll
            for (int p = 0; p < 2; p++) {
                float2 v = up(acc[p][j]);
                G[(c4 + j) * LDS_S + eA + 2 * p]     = sigf(v.x + bb);
                G[(c4 + j) * LDS_S + eA + 2 * p + 1] = sigf(v.y + bb);
            }
        }
    }
    __syncthreads();

    gemm_t2(T, eA, W2s, 64, 0, c4, acc);
#pragma unroll
    for (int p = 0; p < 2; p++) {
        float2 v0 = up(acc[p][0]), v1 = up(acc[p][1]), v2 = up(acc[p][2]), v3 = up(acc[p][3]);
#pragma unroll
        for (int half = 0; half < 2; half++) {
            int node = eA + 2 * p + half;
            int n = nbase + node;
            if (n < NN) {
                float4 o;
                o.x = (half ? v0.y : v0.x) + b2s[c4 + 0] + F0[(c4 + 0) * LDS_S + node];
                o.y = (half ? v1.y : v1.x) + b2s[c4 + 1] + F0[(c4 + 1) * LDS_S + node];
                o.z = (half ? v2.y : v2.x) + b2s[c4 + 2] + F0[(c4 + 2) * LDS_S + node];
                o.w = (half ? v3.y : v3.x) + b2s[c4 + 3] + F0[(c4 + 3) * LDS_S + node];
                *reinterpret_cast<float4*>(&out[(long long)n * 256 + c4]) = o;
            }
        }
    }

#pragma unroll
    for (int i = 0; i < 3; i++) {
        float* Fi = F1arr[i];
        gemm_t2(Fi, eA, W1v, 64, 0, c4, acc);
        __syncthreads();
        {
#pragma unroll
            for (int j = 0; j < 4; j++) {
#pragma unroll
                for (int p = 0; p < 2; p++) {
                    float2 v = up(acc[p][j]);
                    int node = eA + 2 * p;
                    T[(c4 + j) * LDS_S + node]     = v.x * G[(c4 + j) * LDS_S + node];
                    T[(c4 + j) * LDS_S + node + 1] = v.y * G[(c4 + j) * LDS_S + node + 1];
                }
            }
        }
        __syncthreads();
        gemm_t2(T, eA, W2v, 64, 0, c4, acc);
#pragma unroll
        for (int p = 0; p < 2; p++) {
            float2 v0 = up(acc[p][0]), v1 = up(acc[p][1]), v2 = up(acc[p][2]), v3 = up(acc[p][3]);
#pragma unroll
            for (int half = 0; half < 2; half++) {
                int node = eA + 2 * p + half;
                int n = nbase + node;
                if (n < NN) {
                    long long ob = (long long)n * 256 + 64;
                    out[ob + (c4 + 0) * 3 + i] = (half ? v0.y : v0.x) + Fi[(c4 + 0) * LDS_S + node];
                    out[ob + (c4 + 1) * 3 + i] = (half ? v1.y : v1.x) + Fi[(c4 + 1) * LDS_S + node];
                    out[ob + (c4 + 2) * 3 + i] = (half ? v2.y : v2.x) + Fi[(c4 + 2) * LDS_S + node];
                    out[ob + (c4 + 3) * 3 + i] = (half ? v3.y : v3.x) + Fi[(c4 + 3) * LDS_S + node];
                }
            }
        }
    }
}

// ---------------- launch ----------------
extern "C" void kernel_launch(void* const* d_in, const int* in_sizes, int n_in,
                              void* d_out, int out_size) {
    const float* pos       = (const float*)d_in[0];
    const float* embed_W   = (const float*)d_in[1];
    const float* exp_w     = (const float*)d_in[2];
    const float* rad_W1    = (const float*)d_in[3];
    const float* rad_b1    = (const float*)d_in[4];
    const float* rad_W2    = (const float*)d_in[5];
    const float* rad_b2    = (const float*)d_in[6];
    const float* rad_Wdeg  = (const float*)d_in[7];
    const float* rad_bdeg  = (const float*)d_in[8];
    const float* rad_Wattn = (const float*)d_in[9];
    const float* rad_battn = (const float*)d_in[10];
    const float* deg_proj0 = (const float*)d_in[11];
    const float* deg_proj1 = (const float*)d_in[12];
    const float* alpha_dot = (const float*)d_in[13];
    const float* out_proj0 = (const float*)d_in[14];
    const float* out_proj1 = (const float*)d_in[15];
    const float* ffn_W1s   = (const float*)d_in[16];
    const float* ffn_b1s   = (const float*)d_in[17];
    const float* ffn_W1v   = (const float*)d_in[18];
    const float* ffn_W2s   = (const float*)d_in[19];
    const float* ffn_b2s   = (const float*)d_in[20];
    const float* ffn_W2v   = (const float*)d_in[21];
    const int* node_atom   = (const int*)d_in[22];
    const int* edge_src    = (const int*)d_in[23];
    const int* edge_dst    = (const int*)d_in[24];
    float* out = (float*)d_out;

    cudaFuncSetAttribute(k4_node, cudaFuncAttributeMaxDynamicSharedMemorySize, K4_SMEM);

    k0_init<<<1024, 256>>>(embed_W, node_atom);
    k1_edge<<<NE / 64, 128>>>(pos, exp_w, rad_W1, rad_b1, rad_W2, rad_b2,
                              rad_Wdeg, rad_bdeg, rad_Wattn, rad_battn,
                              deg_proj0, deg_proj1, edge_src, edge_dst);
    k2_fused<<<NE / 8, 256>>>(pos, alpha_dot, edge_src, edge_dst);
    k4_node<<<(NN + 63) / 64, 256, K4_SMEM>>>(out_proj0, out_proj1, ffn_W1s, ffn_b1s,
                                              ffn_W1v, ffn_W2s, ffn_b2s, ffn_W2v, out);
}

// round 14
// speedup vs baseline: 1.9656x; 1.1445x over previous
#include <cuda_runtime.h>
#include <cuda_fp16.h>
#include <math.h>
#include <stdint.h>

#define NN 50000
#define NE 800000
#define LDS_S 66

// ---------------- scratch (device globals) ----------------
__device__ float g_f0[NN * 64];
__device__ float g_f1[NN * 192];          // [n][3][64]
__device__ float g_agg0[NN * 64];
__device__ float g_agg1[NN * 192];        // [n][3][64]
__device__ float g_z[NN * 8];
__device__ __half g_wattn_h[256000000];   // E*320
__device__ float g_Wm0[4096];             // INV * Wdeg0 * diag(exp_w) * P0
__device__ float g_Wm1[4096];             // INV * Wdeg1 * diag(exp_w) * P1
__device__ float g_bm0[64];
__device__ float g_bm1[64];

typedef unsigned long long u64;

// ---------------- helpers ----------------
__device__ __forceinline__ float siluf(float x) { return __fdividef(x, 1.f + __expf(-x)); }
__device__ __forceinline__ float sigf(float x) { return __fdividef(1.f, 1.f + __expf(-x)); }

__device__ __forceinline__ u64 pk(float x) {
    u64 r; asm("mov.b64 %0, {%1, %1};" : "=l"(r) : "f"(x)); return r;
}
__device__ __forceinline__ void fma2(u64& d, u64 a, u64 b) {
    asm("fma.rn.f32x2 %0, %1, %2, %0;" : "+l"(d) : "l"(a), "l"(b));
}
__device__ __forceinline__ float2 up(u64 a) {
    float2 v; asm("mov.b64 {%0, %1}, %2;" : "=f"(v.x), "=f"(v.y) : "l"(a)); return v;
}

__device__ __forceinline__ void red_v2(float* p, float a, float b) {
    asm volatile("{ .reg .u64 q; cvta.to.global.u64 q, %0; red.global.add.v2.f32 [q], {%1, %2}; }"
                 :: "l"(p), "f"(a), "f"(b) : "memory");
}
__device__ __forceinline__ void red_v4(float* p, float a, float b, float c, float d) {
    asm volatile("{ .reg .u64 q; cvta.to.global.u64 q, %0; red.global.add.v4.f32 [q], {%1, %2, %3, %4}; }"
                 :: "l"(p), "f"(a), "f"(b), "f"(c), "f"(d) : "memory");
}

// ---------------- K0: init node state ----------------
__global__ void k0_init(const float* __restrict__ embed_W, const int* __restrict__ node_atom) {
    int stride = gridDim.x * blockDim.x;
    for (int i = blockIdx.x * blockDim.x + threadIdx.x; i < NN * 192; i += stride) {
        g_f1[i] = 0.f;
        g_agg1[i] = 0.f;
        if (i < NN * 64) {
            int n = i >> 6, c = i & 63;
            g_f0[i] = embed_W[node_atom[n] * 64 + c];
            g_agg0[i] = 0.f;
        }
        if (i < NN * 8) g_z[i] = 0.f;
    }
}

// ---------------- K0f: fold Wdeg*diag(exp_w)*P into merged weights ----------------
__global__ void k0_fold(const float* __restrict__ Wdeg, const float* __restrict__ bdeg,
                        const float* __restrict__ exp_w,
                        const float* __restrict__ P0, const float* __restrict__ P1) {
    int i = blockIdx.x * 256 + threadIdx.x;
    if (i < 8192) {
        int m = i >> 12;
        int kn = i & 4095;
        int k = kn >> 6, n = kn & 63;
        const float* P = m ? P1 : P0;
        float s = 0.f;
#pragma unroll 8
        for (int c = 0; c < 64; c++)
            s += Wdeg[k * 128 + m * 64 + c] * exp_w[c] * P[c * 64 + n];
        (m ? g_Wm1 : g_Wm0)[kn] = 0.25f * s;
    } else if (i < 8320) {
        int j = i - 8192;
        int m = j >> 6, n = j & 63;
        const float* P = m ? P1 : P0;
        float s = 0.f;
#pragma unroll 8
        for (int c = 0; c < 64; c++)
            s += bdeg[m * 64 + c] * exp_w[c] * P[c * 64 + n];
        (m ? g_bm1 : g_bm0)[n] = 0.25f * s;
    }
}

// ---------------- k-major GEMM, 8 rows (4 pairs) per thread ----------------
__device__ __forceinline__ void gemm_t(const float* __restrict__ As, int eA,
                                       const float* __restrict__ Bg, int ldb,
                                       int colbase, int c4, int K,
                                       u64 acc[4][4]) {
#pragma unroll
    for (int p = 0; p < 4; p++)
#pragma unroll
        for (int j = 0; j < 4; j++) acc[p][j] = 0ull;
    const float* Bp = Bg + colbase + c4;
#pragma unroll 4
    for (int k = 0; k < K; k++) {
        const u64* ap = reinterpret_cast<const u64*>(As + k * LDS_S + eA);
        u64 a0 = ap[0], a1 = ap[1], a2 = ap[2], a3 = ap[3];
        float4 b = *reinterpret_cast<const float4*>(Bp + k * ldb);
        u64 bx = pk(b.x), by = pk(b.y), bz = pk(b.z), bw = pk(b.w);
        fma2(acc[0][0], a0, bx); fma2(acc[0][1], a0, by); fma2(acc[0][2], a0, bz); fma2(acc[0][3], a0, bw);
        fma2(acc[1][0], a1, bx); fma2(acc[1][1], a1, by); fma2(acc[1][2], a1, bz); fma2(acc[1][3], a1, bw);
        fma2(acc[2][0], a2, bx); fma2(acc[2][1], a2, by); fma2(acc[2][2], a2, bz); fma2(acc[2][3], a2, bw);
        fma2(acc[3][0], a3, bx); fma2(acc[3][1], a3, by); fma2(acc[3][2], a3, bz); fma2(acc[3][3], a3, bw);
    }
}

// k-major GEMM, 4 rows (2 pairs) per thread, K=64
__device__ __forceinline__ void gemm_t2(const float* __restrict__ As, int eA,
                                        const float* __restrict__ Bg, int ldb,
                                        int colbase, int c4,
                                        u64 acc[2][4]) {
#pragma unroll
    for (int p = 0; p < 2; p++)
#pragma unroll
        for (int j = 0; j < 4; j++) acc[p][j] = 0ull;
    const float* Bp = Bg + colbase + c4;
#pragma unroll 4
    for (int k = 0; k < 64; k++) {
        const u64* ap = reinterpret_cast<const u64*>(As + k * LDS_S + eA);
        u64 a0 = ap[0], a1 = ap[1];
        float4 b = *reinterpret_cast<const float4*>(Bp + k * ldb);
        u64 bx = pk(b.x), by = pk(b.y), bz = pk(b.z), bw = pk(b.w);
        fma2(acc[0][0], a0, bx); fma2(acc[0][1], a0, by); fma2(acc[0][2], a0, bz); fma2(acc[0][3], a0, bw);
        fma2(acc[1][0], a1, bx); fma2(acc[1][1], a1, by); fma2(acc[1][2], a1, bz); fma2(acc[1][3], a1, bw);
    }
}

// ---------------- K1: edge-tiled radial MLP + merged degree scatter + w_attn ----------------
__global__ void __launch_bounds__(128) k1_edge(
    const float* __restrict__ pos,
    const float* __restrict__ W1, const float* __restrict__ b1,
    const float* __restrict__ W2, const float* __restrict__ b2,
    const float* __restrict__ Wattn, const float* __restrict__ battn,
    const int* __restrict__ esrc, const int* __restrict__ edst)
{
    __shared__ float SA[64 * LDS_S];
    __shared__ float SB[64 * LDS_S];
    __shared__ float sy[3][64];
    __shared__ int sdst[64];
    __shared__ float stmp[2][64];

    int tid = threadIdx.x;
    int cg = tid & 15, c4 = cg << 2;
    int eg = tid >> 4, eA = eg << 3;
    int ebase = blockIdx.x * 64;

    if (tid < 64) {
        int e = ebase + tid;
        int s = esrc[e], d = edst[e];
        float vx = pos[d * 3 + 0] - pos[s * 3 + 0];
        float vy = pos[d * 3 + 1] - pos[s * 3 + 1];
        float vz = pos[d * 3 + 2] - pos[s * 3 + 2];
        float dist = sqrtf(vx * vx + vy * vy + vz * vz + 1e-9f);
        float ri = 1.f / dist;
        const float PI_ = 3.14159265358979323846f;
        float cut = (dist < 5.0f) ? 0.5f * (__cosf(PI_ * dist * 0.2f) + 1.f) : 0.f;
        sdst[tid] = d;
        sy[0][tid] = vx * ri; sy[1][tid] = vy * ri; sy[2][tid] = vz * ri;
        stmp[0][tid] = cut;
        stmp[1][tid] = __expf(-dist);
    }
    __syncthreads();

    {
        const float START = 0.006737946999085467f;
        const float STEP = (1.0f - START) / 49.0f;
        const float BETA = 1.0f / ((0.04f * (1.0f - START)) * (0.04f * (1.0f - START)));
        int er = tid & 63, k0 = tid >> 6;
        float cut = stmp[0][er], expd = stmp[1][er];
        for (int k = k0; k < 50; k += 2) {
            float t = expd - (START + (float)k * STEP);
            SA[k * LDS_S + er] = cut * __expf(-BETA * t * t);
        }
    }
    __syncthreads();

    u64 acc[4][4];

    // GEMM1: rbf(50) -> 64, silu -> SB
    gemm_t(SA, eA, W1, 64, 0, c4, 50, acc);
    {
#pragma unroll
        for (int j = 0; j < 4; j++) {
            float bb = b1[c4 + j];
#pragma unroll
            for (int p = 0; p < 4; p++) {
                float2 v = up(acc[p][j]);
                v.x = siluf(v.x + bb); v.y = siluf(v.y + bb);
                *reinterpret_cast<float2*>(&SB[(c4 + j) * LDS_S + eA + 2 * p]) = v;
            }
        }
    }
    __syncthreads();

    // GEMM2: 64 -> 64, silu -> SA (h2)
    gemm_t(SB, eA, W2, 64, 0, c4, 64, acc);
    {
#pragma unroll
        for (int j = 0; j < 4; j++) {
            float bb = b2[c4 + j];
#pragma unroll
            for (int p = 0; p < 4; p++) {
                float2 v = up(acc[p][j]);
                v.x = siluf(v.x + bb); v.y = siluf(v.y + bb);
                *reinterpret_cast<float2*>(&SA[(c4 + j) * LDS_S + eA + 2 * p]) = v;
            }
        }
    }
    __syncthreads();

    // w_attn: 5 chunks of 64 -> fp16 global
    for (int ch = 0; ch < 5; ch++) {
        gemm_t(SA, eA, Wattn, 320, ch * 64, c4, 64, acc);
        int col = ch * 64 + c4;
        float b0v = battn[col], b1v = battn[col + 1], b2v = battn[col + 2], b3v = battn[col + 3];
#pragma unroll
        for (int p = 0; p < 4; p++) {
            float2 v0 = up(acc[p][0]), v1 = up(acc[p][1]), v2 = up(acc[p][2]), v3 = up(acc[p][3]);
            long long wbA = (long long)(ebase + eA + 2 * p) * 320 + col;
            long long wbB = wbA + 320;
            *reinterpret_cast<__half2*>(&g_wattn_h[wbA])     = __floats2half2_rn(v0.x + b0v, v1.x + b1v);
            *reinterpret_cast<__half2*>(&g_wattn_h[wbA + 2]) = __floats2half2_rn(v2.x + b2v, v3.x + b3v);
            *reinterpret_cast<__half2*>(&g_wattn_h[wbB])     = __floats2half2_rn(v0.y + b0v, v1.y + b1v);
            *reinterpret_cast<__half2*>(&g_wattn_h[wbB + 2]) = __floats2half2_rn(v2.y + b2v, v3.y + b3v);
        }
    }

    // merged deg chunk 0: f0 scatter = h2 @ Wm0 + bm0 (INV folded in)
    gemm_t(SA, eA, g_Wm0, 64, 0, c4, 64, acc);
    {
        float b0v = g_bm0[c4], b1v = g_bm0[c4 + 1], b2v = g_bm0[c4 + 2], b3v = g_bm0[c4 + 3];
#pragma unroll
        for (int p = 0; p < 4; p++) {
            int dA = sdst[eA + 2 * p], dB = sdst[eA + 2 * p + 1];
            float2 v0 = up(acc[p][0]), v1 = up(acc[p][1]), v2 = up(acc[p][2]), v3 = up(acc[p][3]);
            red_v4(&g_f0[dA * 64 + c4], v0.x + b0v, v1.x + b1v, v2.x + b2v, v3.x + b3v);
            red_v4(&g_f0[dB * 64 + c4], v0.y + b0v, v1.y + b1v, v2.y + b2v, v3.y + b3v);
        }
    }

    // merged deg chunk 1: f1 scatter = (h2 @ Wm1 + bm1) x Y
    gemm_t(SA, eA, g_Wm1, 64, 0, c4, 64, acc);
    {
        float b0v = g_bm1[c4], b1v = g_bm1[c4 + 1], b2v = g_bm1[c4 + 2], b3v = g_bm1[c4 + 3];
#pragma unroll
        for (int p = 0; p < 4; p++) {
            float2 v0 = up(acc[p][0]), v1 = up(acc[p][1]), v2 = up(acc[p][2]), v3 = up(acc[p][3]);
#pragma unroll
            for (int half = 0; half < 2; half++) {
                int el = eA + 2 * p + half;
                int d = sdst[el];
                float a0 = (half ? v0.y : v0.x) + b0v;
                float a1 = (half ? v1.y : v1.x) + b1v;
                float a2 = (half ? v2.y : v2.x) + b2v;
                float a3 = (half ? v3.y : v3.x) + b3v;
                float* pp = &g_f1[d * 192];
#pragma unroll
                for (int i = 0; i < 3; i++) {
                    float yy = sy[i][el];
                    red_v4(pp + i * 64 + c4, a0 * yy, a1 * yy, a2 * yy, a3 * yy);
                }
            }
        }
    }
}

// ---------------- K2: fused messages + softmax-weight + aggregation ----------------
__global__ void __launch_bounds__(256) k2_fused(
    const float* __restrict__ pos, const float* __restrict__ alpha_dot,
    const int* __restrict__ esrc, const int* __restrict__ edst)
{
    int warp = threadIdx.x >> 5, lane = threadIdx.x & 31;
    int e = blockIdx.x * 8 + warp;
    if (e >= NE) return;
    int s = esrc[e], d = edst[e];
    float vx = pos[d * 3 + 0] - pos[s * 3 + 0];
    float vy = pos[d * 3 + 1] - pos[s * 3 + 1];
    float vz = pos[d * 3 + 2] - pos[s * 3 + 2];
    float ri = rsqrtf(vx * vx + vy * vy + vz * vz + 1e-9f);
    float y0 = vx * ri, y1 = vy * ri, y2 = vz * ri;

    int c = lane << 1;
    float2 s0 = *reinterpret_cast<const float2*>(&g_f0[s * 64 + c]);
    const float* f1p = &g_f1[s * 192 + c];
    float2 sv0 = *reinterpret_cast<const float2*>(f1p + 0 * 64);
    float2 sv1 = *reinterpret_cast<const float2*>(f1p + 1 * 64);
    float2 sv2 = *reinterpret_cast<const float2*>(f1p + 2 * 64);

    const __half2* wp = reinterpret_cast<const __half2*>(&g_wattn_h[(long long)e * 320 + c]);
    float2 w0 = __half22float2(wp[0]);
    float2 w1 = __half22float2(wp[32]);
    float2 w2 = __half22float2(wp[64]);
    float2 w3 = __half22float2(wp[96]);
    float2 w4 = __half22float2(wp[128]);

    const float IS3 = 0.57735026918962576f;
    const float IS2 = 0.70710678118654752f;

    float dvx = sv0.x * y0 + sv1.x * y1 + sv2.x * y2;
    float dvy = sv0.y * y0 + sv1.y * y1 + sv2.y * y2;
    float m0x = w0.x * s0.x + w3.x * dvx * IS3;
    float m0y = w0.y * s0.y + w3.y * dvy * IS3;

    float cx0x = sv1.x * y2 - sv2.x * y1, cx1x = sv2.x * y0 - sv0.x * y2, cx2x = sv0.x * y1 - sv1.x * y0;
    float cx0y = sv1.y * y2 - sv2.y * y1, cx1y = sv2.y * y0 - sv0.y * y2, cx2y = sv0.y * y1 - sv1.y * y0;
    float w1sx = w1.x * s0.x, w1sy = w1.y * s0.y;
    float m1x0 = w1sx * y0 + w2.x * sv0.x + w4.x * cx0x * IS2;
    float m1x1 = w1sx * y1 + w2.x * sv1.x + w4.x * cx1x * IS2;
    float m1x2 = w1sx * y2 + w2.x * sv2.x + w4.x * cx2x * IS2;
    float m1y0 = w1sy * y0 + w2.y * sv0.y + w4.y * cx0y * IS2;
    float m1y1 = w1sy * y1 + w2.y * sv1.y + w4.y * cx1y * IS2;
    float m1y2 = w1sy * y2 + w2.y * sv2.y + w4.y * cx2y * IS2;

    float slrx = 0.2f * m0x + 0.8f * m0x * sigf(m0x);
    float slry = 0.2f * m0y + 0.8f * m0y * sigf(m0y);
    float p = slrx * alpha_dot[c] + slry * alpha_dot[c + 1];
    p += __shfl_xor_sync(0xffffffffu, p, 2);
    p += __shfl_xor_sync(0xffffffffu, p, 1);
    float ea = __expf(p);

    if ((lane & 3) == 0) atomicAdd(&g_z[d * 8 + (lane >> 2)], ea);

    red_v2(&g_agg0[d * 64 + c], ea * m0x, ea * m0y);
    float* ap = &g_agg1[d * 192 + c];
    red_v2(ap + 0 * 64, ea * m1x0, ea * m1y0);
    red_v2(ap + 1 * 64, ea * m1x1, ea * m1y1);
    red_v2(ap + 2 * 64, ea * m1x2, ea * m1y2);
}

// ---------------- K4: tiled node update (64 nodes / block) ----------------
#define SOFF_T   0
#define SOFF_F0  4224
#define SOFF_F10 8448
#define SOFF_F11 12672
#define SOFF_F12 16896
#define SOFF_G   21120
#define K4_SMEM  (25344 * 4)

__global__ void __launch_bounds__(256) k4_node(
    const float* __restrict__ P0, const float* __restrict__ P1,
    const float* __restrict__ W1s, const float* __restrict__ b1s,
    const float* __restrict__ W1v, const float* __restrict__ W2s,
    const float* __restrict__ b2s, const float* __restrict__ W2v,
    float* __restrict__ out)
{
    extern __shared__ float sm4[];
    float* T  = sm4 + SOFF_T;
    float* F0 = sm4 + SOFF_F0;
    float* F1a = sm4 + SOFF_F10;
    float* F1b = sm4 + SOFF_F11;
    float* F1c = sm4 + SOFF_F12;
    float* G  = sm4 + SOFF_G;
    float* F1arr[3] = {F1a, F1b, F1c};

    int tid = threadIdx.x;
    int cg = tid & 15, c4 = cg << 2;
    int eA = (tid >> 4) << 2;
    int nbase = blockIdx.x * 64;

    for (int idx = tid; idx < 4096; idx += 256) {
        int node = idx >> 6, c = idx & 63;
        int n = nbase + node; if (n >= NN) n = NN - 1;
        float z = g_z[n * 8 + (c >> 3)];
        float rz = z > 0.f ? __fdividef(1.f, z) : 0.f;
        T[c * LDS_S + node]   = g_agg0[n * 64 + c] * rz;
        F1a[c * LDS_S + node] = g_agg1[n * 192 + c] * rz;
        F1b[c * LDS_S + node] = g_agg1[n * 192 + 64 + c] * rz;
        F1c[c * LDS_S + node] = g_agg1[n * 192 + 128 + c] * rz;
    }
    __syncthreads();

    u64 acc[2][4];

    gemm_t2(T, eA, P0, 64, 0, c4, acc);
#pragma unroll
    for (int p = 0; p < 2; p++) {
        int na = nbase + eA + 2 * p, nb = na + 1;
        int la = na < NN ? na : NN - 1, lb = nb < NN ? nb : NN - 1;
        float4 ra = *reinterpret_cast<const float4*>(&g_f0[la * 64 + c4]);
        float4 rb = *reinterpret_cast<const float4*>(&g_f0[lb * 64 + c4]);
        float2 v0 = up(acc[p][0]), v1 = up(acc[p][1]), v2 = up(acc[p][2]), v3 = up(acc[p][3]);
        int ea2 = eA + 2 * p;
        F0[(c4 + 0) * LDS_S + ea2] = v0.x + ra.x;  F0[(c4 + 0) * LDS_S + ea2 + 1] = v0.y + rb.x;
        F0[(c4 + 1) * LDS_S + ea2] = v1.x + ra.y;  F0[(c4 + 1) * LDS_S + ea2 + 1] = v1.y + rb.y;
        F0[(c4 + 2) * LDS_S + ea2] = v2.x + ra.z;  F0[(c4 + 2) * LDS_S + ea2 + 1] = v2.y + rb.z;
        F0[(c4 + 3) * LDS_S + ea2] = v3.x + ra.w;  F0[(c4 + 3) * LDS_S + ea2 + 1] = v3.y + rb.w;
    }

#pragma unroll
    for (int i = 0; i < 3; i++) {
        float* Fi = F1arr[i];
        gemm_t2(Fi, eA, P1, 64, 0, c4, acc);
        __syncthreads();
#pragma unroll
        for (int p = 0; p < 2; p++) {
            int na = nbase + eA + 2 * p, nb = na + 1;
            int la = na < NN ? na : NN - 1, lb = nb < NN ? nb : NN - 1;
            float4 ra = *reinterpret_cast<const float4*>(&g_f1[la * 192 + i * 64 + c4]);
            float4 rb = *reinterpret_cast<const float4*>(&g_f1[lb * 192 + i * 64 + c4]);
            float2 v0 = up(acc[p][0]), v1 = up(acc[p][1]), v2 = up(acc[p][2]), v3 = up(acc[p][3]);
            int ea2 = eA + 2 * p;
            Fi[(c4 + 0) * LDS_S + ea2] = v0.x + ra.x;  Fi[(c4 + 0) * LDS_S + ea2 + 1] = v0.y + rb.x;
            Fi[(c4 + 1) * LDS_S + ea2] = v1.x + ra.y;  Fi[(c4 + 1) * LDS_S + ea2 + 1] = v1.y + rb.y;
            Fi[(c4 + 2) * LDS_S + ea2] = v2.x + ra.z;  Fi[(c4 + 2) * LDS_S + ea2 + 1] = v2.y + rb.z;
            Fi[(c4 + 3) * LDS_S + ea2] = v3.x + ra.w;  Fi[(c4 + 3) * LDS_S + ea2 + 1] = v3.y + rb.w;
        }
        __syncthreads();
    }

    gemm_t2(F0, eA, W1s, 128, 0, c4, acc);
    {
#pragma unroll
        for (int j = 0; j < 4; j++) {
            float bb = b1s[c4 + j];
#pragma unroll
            for (int p = 0; p < 2; p++) {
                float2 v = up(acc[p][j]);
                T[(c4 + j) * LDS_S + eA + 2 * p]     = siluf(v.x + bb);
                T[(c4 + j) * LDS_S + eA + 2 * p + 1] = siluf(v.y + bb);
            }
        }
    }
    gemm_t2(F0, eA, W1s, 128, 64, c4, acc);
    {
#pragma unroll
        for (int j = 0; j < 4; j++) {
            float bb = b1s[64 + c4 + j];
#pragma unroll
            for (int p = 0; p < 2; p++) {
                float2 v = up(acc[p][j]);
                G[(c4 + j) * LDS_S + eA + 2 * p]     = sigf(v.x + bb);
                G[(c4 + j) * LDS_S + eA + 2 * p + 1] = sigf(v.y + bb);
            }
        }
    }
    __syncthreads();

    gemm_t2(T, eA, W2s, 64, 0, c4, acc);
#pragma unroll
    for (int p = 0; p < 2; p++) {
        float2 v0 = up(acc[p][0]), v1 = up(acc[p][1]), v2 = up(acc[p][2]), v3 = up(acc[p][3]);
#pragma unroll
        for (int half = 0; half < 2; half++) {
            int node = eA + 2 * p + half;
            int n = nbase + node;
            if (n < NN) {
                float4 o;
                o.x = (half ? v0.y : v0.x) + b2s[c4 + 0] + F0[(c4 + 0) * LDS_S + node];
                o.y = (half ? v1.y : v1.x) + b2s[c4 + 1] + F0[(c4 + 1) * LDS_S + node];
                o.z = (half ? v2.y : v2.x) + b2s[c4 + 2] + F0[(c4 + 2) * LDS_S + node];
                o.w = (half ? v3.y : v3.x) + b2s[c4 + 3] + F0[(c4 + 3) * LDS_S + node];
                *reinterpret_cast<float4*>(&out[(long long)n * 256 + c4]) = o;
            }
        }
    }

#pragma unroll
    for (int i = 0; i < 3; i++) {
        float* Fi = F1arr[i];
        gemm_t2(Fi, eA, W1v, 64, 0, c4, acc);
        __syncthreads();
        {
#pragma unroll
            for (int j = 0; j < 4; j++) {
#pragma unroll
                for (int p = 0; p < 2; p++) {
                    float2 v = up(acc[p][j]);
                    int node = eA + 2 * p;
                    T[(c4 + j) * LDS_S + node]     = v.x * G[(c4 + j) * LDS_S + node];
                    T[(c4 + j) * LDS_S + node + 1] = v.y * G[(c4 + j) * LDS_S + node + 1];
                }
            }
        }
        __syncthreads();
        gemm_t2(T, eA, W2v, 64, 0, c4, acc);
#pragma unroll
        for (int p = 0; p < 2; p++) {
            float2 v0 = up(acc[p][0]), v1 = up(acc[p][1]), v2 = up(acc[p][2]), v3 = up(acc[p][3]);
#pragma unroll
            for (int half = 0; half < 2; half++) {
                int node = eA + 2 * p + half;
                int n = nbase + node;
                if (n < NN) {
                    long long ob = (long long)n * 256 + 64;
                    out[ob + (c4 + 0) * 3 + i] = (half ? v0.y : v0.x) + Fi[(c4 + 0) * LDS_S + node];
                    out[ob + (c4 + 1) * 3 + i] = (half ? v1.y : v1.x) + Fi[(c4 + 1) * LDS_S + node];
                    out[ob + (c4 + 2) * 3 + i] = (half ? v2.y : v2.x) + Fi[(c4 + 2) * LDS_S + node];
                    out[ob + (c4 + 3) * 3 + i] = (half ? v3.y : v3.x) + Fi[(c4 + 3) * LDS_S + node];
                }
            }
        }
    }
}

// ---------------- launch ----------------
extern "C" void kernel_launch(void* const* d_in, const int* in_sizes, int n_in,
                              void* d_out, int out_size) {
    const float* pos       = (const float*)d_in[0];
    const float* embed_W   = (const float*)d_in[1];
    const float* exp_w     = (const float*)d_in[2];
    const float* rad_W1    = (const float*)d_in[3];
    const float* rad_b1    = (const float*)d_in[4];
    const float* rad_W2    = (const float*)d_in[5];
    const float* rad_b2    = (const float*)d_in[6];
    const float* rad_Wdeg  = (const float*)d_in[7];
    const float* rad_bdeg  = (const float*)d_in[8];
    const float* rad_Wattn = (const float*)d_in[9];
    const float* rad_battn = (const float*)d_in[10];
    const float* deg_proj0 = (const float*)d_in[11];
    const float* deg_proj1 = (const float*)d_in[12];
    const float* alpha_dot = (const float*)d_in[13];
    const float* out_proj0 = (const float*)d_in[14];
    const float* out_proj1 = (const float*)d_in[15];
    const float* ffn_W1s   = (const float*)d_in[16];
    const float* ffn_b1s   = (const float*)d_in[17];
    const float* ffn_W1v   = (const float*)d_in[18];
    const float* ffn_W2s   = (const float*)d_in[19];
    const float* ffn_b2s   = (const float*)d_in[20];
    const float* ffn_W2v   = (const float*)d_in[21];
    const int* node_atom   = (const int*)d_in[22];
    const int* edge_src    = (const int*)d_in[23];
    const int* edge_dst    = (const int*)d_in[24];
    float* out = (float*)d_out;

    cudaFuncSetAttribute(k4_node, cudaFuncAttributeMaxDynamicSharedMemorySize, K4_SMEM);

    k0_init<<<1024, 256>>>(embed_W, node_atom);
    k0_fold<<<33, 256>>>(rad_Wdeg, rad_bdeg, exp_w, deg_proj0, deg_proj1);
    k1_edge<<<NE / 64, 128>>>(pos, rad_W1, rad_b1, rad_W2, rad_b2,
                              rad_Wattn, rad_battn, edge_src, edge_dst);
    k2_fused<<<NE / 8, 256>>>(pos, alpha_dot, edge_src, edge_dst);
    k4_node<<<(NN + 63) / 64, 256, K4_SMEM>>>(out_proj0, out_proj1, ffn_W1s, ffn_b1s,
                                              ffn_W1v, ffn_W2s, ffn_b2s, ffn_W2v, out);
}